// round 6
// baseline (speedup 1.0000x reference)
#include <cuda_runtime.h>

#define NMAX 50000
#define ACC4 (NMAX * 3)   // float4 count in accumulator

// ---- scratch (static __device__, zero-initialized at module load) ----
// Invariant: g_accum is all-zero at entry of every kernel_launch call.
// k_edge accumulates into it; k_out reads it and writes zeros back.
__device__ float4 g_accum[ACC4];   // per node: [denom(4)][T0(4)][T1(4)]
__device__ float  g_consts[20];    // s0[4] s1[4] d0[4] d1[4] g[4]
__device__ float  g_easum;

// K0: single block — 20 head constants + easum reset. ~1us.
__global__ void k_init(const float* __restrict__ W, const float* __restrict__ att_src,
                       const float* __restrict__ att_dst, const float* __restrict__ W_edge,
                       const float* __restrict__ att_edge) {
    int t = threadIdx.x;        // 256 threads = H*C
    __shared__ float sh[5][256];
    int h = t >> 6;
    float w0 = W[2 * t], w1 = W[2 * t + 1];
    float as = att_src[t], ad = att_dst[t];
    sh[0][t] = w0 * as;
    sh[1][t] = w1 * as;
    sh[2][t] = w0 * ad;
    sh[3][t] = w1 * ad;
    sh[4][t] = W_edge[t] * att_edge[t];
    __syncthreads();
    for (int off = 32; off >= 1; off >>= 1) {
        if ((t & 63) < off) {
            #pragma unroll
            for (int k = 0; k < 5; k++) sh[k][t] += sh[k][t + off];
        }
        __syncthreads();
    }
    if ((t & 63) == 0) {
        #pragma unroll
        for (int k = 0; k < 5; k++) g_consts[k * 4 + h] = sh[k][t];
    }
    if (t == 0) g_easum = 0.f;
}

__device__ __forceinline__ void red_v4(float4* p, float a, float b, float c, float d) {
    asm volatile("red.global.add.v4.f32 [%0], {%1,%2,%3,%4};"
                 :: "l"(p), "f"(a), "f"(b), "f"(c), "f"(d) : "memory");
}

struct C20 {
    float s0[4], s1[4], d0[4], d1[4], g[4];
};

__device__ __forceinline__ void edge_body(const float2* __restrict__ x2,
                                          int src, int dst, float w, int N, const C20& c) {
    if ((unsigned)src >= (unsigned)N || (unsigned)dst >= (unsigned)N) return;
    float2 xs = __ldg(&x2[src]);
    float2 xd = __ldg(&x2[dst]);
    float a0 = xs.x * c.s0[0] + xs.y * c.s1[0] + xd.x * c.d0[0] + xd.y * c.d1[0] + w * c.g[0];
    float a1 = xs.x * c.s0[1] + xs.y * c.s1[1] + xd.x * c.d0[1] + xd.y * c.d1[1] + w * c.g[1];
    float a2 = xs.x * c.s0[2] + xs.y * c.s1[2] + xd.x * c.d0[2] + xd.y * c.d1[2] + w * c.g[2];
    float a3 = xs.x * c.s0[3] + xs.y * c.s1[3] + xd.x * c.d0[3] + xd.y * c.d1[3] + w * c.g[3];
    a0 = fmaxf(a0, 0.2f * a0);
    a1 = fmaxf(a1, 0.2f * a1);
    a2 = fmaxf(a2, 0.2f * a2);
    a3 = fmaxf(a3, 0.2f * a3);
    float e0 = __expf(a0), e1 = __expf(a1), e2 = __expf(a2), e3 = __expf(a3);
    float4* base = &g_accum[dst * 3];
    red_v4(base,     e0,        e1,        e2,        e3);
    red_v4(base + 1, e0 * xs.x, e1 * xs.x, e2 * xs.x, e3 * xs.x);
    red_v4(base + 2, e0 * xs.y, e1 * xs.y, e2 * xs.y, e3 * xs.y);
}

// K1: edge pass — 2 edges/thread, front-batched loads; + easum block reduce
__global__ void k_edge(const int* __restrict__ ei, const float* __restrict__ ea,
                       const float* __restrict__ x, int E, int N) {
    C20 c;
    #pragma unroll
    for (int h = 0; h < 4; h++) {
        c.s0[h] = g_consts[h];
        c.s1[h] = g_consts[4 + h];
        c.d0[h] = g_consts[8 + h];
        c.d1[h] = g_consts[12 + h];
        c.g[h]  = g_consts[16 + h];
    }
    const float2* x2 = (const float2*)x;
    int base = blockIdx.x * (blockDim.x * 2) + threadIdx.x;
    int e0 = base, e1 = base + blockDim.x;
    float wsum = 0.f;

    int s0 = 0, d0 = 0, s1 = 0, d1 = 0;
    float w0 = 0.f, w1 = 0.f;
    bool v0 = e0 < E, v1 = e1 < E;
    if (v0) { s0 = __ldg(&ei[e0]); d0 = __ldg(&ei[E + e0]); w0 = __ldg(&ea[e0]); }
    if (v1) { s1 = __ldg(&ei[e1]); d1 = __ldg(&ei[E + e1]); w1 = __ldg(&ea[e1]); }
    if (v0) { wsum += w0; edge_body(x2, s0, d0, w0, N, c); }
    if (v1) { wsum += w1; edge_body(x2, s1, d1, w1, N, c); }

    #pragma unroll
    for (int o = 16; o; o >>= 1) wsum += __shfl_down_sync(0xffffffffu, wsum, o);
    __shared__ float sh[8];
    if ((threadIdx.x & 31) == 0) sh[threadIdx.x >> 5] = wsum;
    __syncthreads();
    if (threadIdx.x == 0) {
        float s = 0.f;
        #pragma unroll
        for (int i = 0; i < 8; i++) s += sh[i];
        atomicAdd(&g_easum, s);
    }
}

// K2: per-node expansion to [N, 256]; self-loop folded analytically.
// 64 threads/node row (float4 stores), block covers 4 nodes.
// Also RESETS this node's accumulators to zero for the next replay.
__global__ void k_out(const float* __restrict__ W, const float* __restrict__ bias,
                      const float* __restrict__ x, float* __restrict__ out,
                      int N, float invE) {
    int t = threadIdx.x;
    int sub = t & 63;
    int h = sub >> 4;            // hc0 = sub*4; h = hc0/64 = sub/16
    const float4* W4 = (const float4*)W;
    float4 wa = W4[sub * 2];
    float4 wb = W4[sub * 2 + 1];
    float4 b4 = ((const float4*)bias)[sub];
    float mean = g_easum * invE;
    float s0 = g_consts[h], s1 = g_consts[4 + h];
    float d0 = g_consts[8 + h], d1 = g_consts[12 + h];
    float gh = g_consts[16 + h];

    int n = blockIdx.x * 4 + (t >> 6);
    bool valid = n < N;

    float4 dd4 = make_float4(0, 0, 0, 0), t04 = dd4, t14 = dd4;
    float2 xn = make_float2(0, 0);
    if (valid) {
        xn  = ((const float2*)x)[n];
        dd4 = g_accum[n * 3 + 0];
        t04 = g_accum[n * 3 + 1];
        t14 = g_accum[n * 3 + 2];
    }
    __syncthreads();   // all reads of g_accum done before resets below
    if (valid && sub < 3) g_accum[n * 3 + sub] = make_float4(0, 0, 0, 0);
    if (!valid) return;

    float dh  = (h == 0) ? dd4.x : (h == 1) ? dd4.y : (h == 2) ? dd4.z : dd4.w;
    float t0h = (h == 0) ? t04.x : (h == 1) ? t04.y : (h == 2) ? t04.z : t04.w;
    float t1h = (h == 0) ? t14.x : (h == 1) ? t14.y : (h == 2) ? t14.z : t14.w;

    // self-loop logit: a_src[n,h] + a_dst[n,h] + mean*g[h]
    float a = xn.x * s0 + xn.y * s1 + xn.x * d0 + xn.y * d1 + mean * gh;
    a = fmaxf(a, 0.2f * a);
    float ws = __expf(a);
    float rdenom = 1.0f / (dh + ws);
    float T0 = (t0h + ws * xn.x) * rdenom;
    float T1 = (t1h + ws * xn.y) * rdenom;

    float4 o;
    o.x = T0 * wa.x + T1 * wa.y + b4.x;
    o.y = T0 * wa.z + T1 * wa.w + b4.y;
    o.z = T0 * wb.x + T1 * wb.y + b4.z;
    o.w = T0 * wb.z + T1 * wb.w + b4.w;
    ((float4*)out)[(size_t)n * 64 + sub] = o;
}

extern "C" void kernel_launch(void* const* d_in, const int* in_sizes, int n_in,
                              void* d_out, int out_size) {
    const float* x        = (const float*)d_in[0];
    const int*   ei       = (const int*)d_in[1];     // int32 (JAX x64 off)
    const float* ea       = (const float*)d_in[2];
    const float* W        = (const float*)d_in[3];
    const float* att_src  = (const float*)d_in[4];
    const float* att_dst  = (const float*)d_in[5];
    const float* W_edge   = (const float*)d_in[6];
    const float* att_edge = (const float*)d_in[7];
    const float* bias     = (const float*)d_in[8];
    int N = in_sizes[0] / 2;
    int E = in_sizes[2];
    float* out = (float*)d_out;

    k_init<<<1, 256>>>(W, att_src, att_dst, W_edge, att_edge);
    k_edge<<<(E + 511) / 512, 256>>>(ei, ea, x, E, N);
    k_out<<<(N + 3) / 4, 256>>>(W, bias, x, out, N, 1.0f / (float)E);
}